// round 1
// baseline (speedup 1.0000x reference)
#include <cuda_runtime.h>

// Problem dims
constexpr int kS = 96;     // sequence (i and j)
constexpr int kB = 16;     // batch
constexpr int kD = 512;    // embed dim
constexpr int kH = 128;    // hidden
constexpr int kRows = kS * kB;   // 1536 flattened (i,b) rows

// Scratch: g_h[0] = ha (+0), g_h[1] = hb.  1536*128*4B * 2 = 1.57 MB
__device__ float g_h[2][kRows * kH];

// ---------------------------------------------------------------------------
// Kernel A: ha[r][h] = dot(embeds[r][0:512], W1[h][0:512])
//           hb[r][h] = dot(embeds_cmp[r][0:512], W1[h][512:1024])
// BM=32, BN=128, BK=32, 256 threads, 4x4 microtile per thread.
// ---------------------------------------------------------------------------
__global__ __launch_bounds__(256) void gemm1_kernel(
    const float* __restrict__ embeds, const float* __restrict__ embeds_cmp,
    const float* __restrict__ W1)
{
    const int which = blockIdx.y;
    const float* src = which ? embeds_cmp : embeds;
    const int wcol = which ? kD : 0;
    float* dst = g_h[which];
    const int row0 = blockIdx.x * 32;

    __shared__ float As[32][36];    // [k][m], pad 36 -> aligned float4 reads
    __shared__ float Bs[32][132];   // [k][h], pad 132 -> conflict-free float4 reads

    const int tid = threadIdx.x;
    const int tx = tid & 31;        // h-group (column)
    const int ty = tid >> 5;        // m-group (row)

    float acc[4][4] = {};

    for (int k0 = 0; k0 < kD; k0 += 32) {
        // Load A tile: 32 rows x 32 k (one float4 per thread)
        {
            int m = tid >> 3, k4 = tid & 7;
            float4 v = *(const float4*)&src[(row0 + m) * kD + k0 + k4 * 4];
            As[k4 * 4 + 0][m] = v.x;
            As[k4 * 4 + 1][m] = v.y;
            As[k4 * 4 + 2][m] = v.z;
            As[k4 * 4 + 3][m] = v.w;
        }
        // Load B tile: 128 h x 32 k, stored transposed (4 float4 per thread)
        #pragma unroll
        for (int t = 0; t < 4; t++) {
            int idx = tid + t * 256;          // 0..1023
            int h = idx >> 3, k4 = idx & 7;
            float4 v = *(const float4*)&W1[h * (2 * kD) + wcol + k0 + k4 * 4];
            Bs[k4 * 4 + 0][h] = v.x;
            Bs[k4 * 4 + 1][h] = v.y;
            Bs[k4 * 4 + 2][h] = v.z;
            Bs[k4 * 4 + 3][h] = v.w;
        }
        __syncthreads();

        #pragma unroll
        for (int kk = 0; kk < 32; kk++) {
            float4 a  = *(const float4*)&As[kk][ty * 4];
            float4 bv = *(const float4*)&Bs[kk][tx * 4];
            float am[4] = {a.x, a.y, a.z, a.w};
            float bn[4] = {bv.x, bv.y, bv.z, bv.w};
            #pragma unroll
            for (int m2 = 0; m2 < 4; m2++)
                #pragma unroll
                for (int n2 = 0; n2 < 4; n2++)
                    acc[m2][n2] = fmaf(am[m2], bn[n2], acc[m2][n2]);
        }
        __syncthreads();
    }

    #pragma unroll
    for (int m2 = 0; m2 < 4; m2++) {
        float4 v = make_float4(acc[m2][0], acc[m2][1], acc[m2][2], acc[m2][3]);
        *(float4*)&dst[(row0 + ty * 4 + m2) * kH + tx * 4] = v;
    }
}

// ---------------------------------------------------------------------------
// Kernel B: logits[i,j,b,c] = sum_h relu(ha[i,b,h]+hb[j,b,h]+b1[h]) * W2[c,h] + b2[c]
// Block = (8 i's, one b, all 96 j). 256 threads: tx = j lane (3 j's each), i = tid>>5.
// Dynamic smem: hb[96][132] + ha[8][128] + w2[256]  = 55808 B
// ---------------------------------------------------------------------------
constexpr int kSmemB = (96 * 132 + 8 * 128 + 256) * 4;

__global__ __launch_bounds__(256) void pairwise_kernel(
    const float* __restrict__ b1, const float* __restrict__ W2,
    const float* __restrict__ b2, float* __restrict__ out)
{
    extern __shared__ float sm[];
    float* hb_s = sm;                  // [96][132] padded
    float* ha_s = sm + 96 * 132;       // [8][128]  (b1 folded in)
    float* w2_s = ha_s + 8 * 128;      // [2][128]

    const int b  = blockIdx.y;
    const int i0 = blockIdx.x * 8;
    const int tid = threadIdx.x;

    // hb tile: all 96 j rows for this b (12 float4 per thread)
    #pragma unroll
    for (int t = 0; t < 12; t++) {
        int idx = tid + t * 256;       // 3072 float4s
        int j = idx >> 5, h4 = idx & 31;
        float4 v = *(const float4*)&g_h[1][(j * kB + b) * kH + h4 * 4];
        *(float4*)&hb_s[j * 132 + h4 * 4] = v;
    }
    // ha tile + b1 (1 float4 per thread)
    {
        int i = tid >> 5, h4 = tid & 31;
        float4 v  = *(const float4*)&g_h[0][((i0 + i) * kB + b) * kH + h4 * 4];
        float4 bb = *(const float4*)&b1[h4 * 4];
        v.x += bb.x; v.y += bb.y; v.z += bb.z; v.w += bb.w;
        *(float4*)&ha_s[i * 128 + h4 * 4] = v;
    }
    w2_s[tid] = W2[tid];               // 256 elements exactly
    const float bias0 = b2[0];
    const float bias1 = b2[1];
    __syncthreads();

    const int tx = tid & 31;
    const int i  = tid >> 5;
    const float* hap = &ha_s[i * 128];

    float acc[3][2] = {};

    #pragma unroll 4
    for (int h4 = 0; h4 < 32; h4++) {
        float4 a   = *(const float4*)&hap[h4 * 4];          // broadcast
        float4 w0  = *(const float4*)&w2_s[h4 * 4];         // broadcast
        float4 w1v = *(const float4*)&w2_s[128 + h4 * 4];   // broadcast
        #pragma unroll
        for (int jj = 0; jj < 3; jj++) {
            int j = tx + jj * 32;
            float4 hv = *(const float4*)&hb_s[j * 132 + h4 * 4];
            float v0 = fmaxf(a.x + hv.x, 0.0f);
            float v1 = fmaxf(a.y + hv.y, 0.0f);
            float v2 = fmaxf(a.z + hv.z, 0.0f);
            float v3 = fmaxf(a.w + hv.w, 0.0f);
            float c0 = acc[jj][0], c1 = acc[jj][1];
            c0 = fmaf(v0, w0.x, c0);  c1 = fmaf(v0, w1v.x, c1);
            c0 = fmaf(v1, w0.y, c0);  c1 = fmaf(v1, w1v.y, c1);
            c0 = fmaf(v2, w0.z, c0);  c1 = fmaf(v2, w1v.z, c1);
            c0 = fmaf(v3, w0.w, c0);  c1 = fmaf(v3, w1v.w, c1);
            acc[jj][0] = c0; acc[jj][1] = c1;
        }
    }

    #pragma unroll
    for (int jj = 0; jj < 3; jj++) {
        int j = tx + jj * 32;
        size_t o = ((size_t)((i0 + i) * kS + j) * kB + b) * 2;
        *(float2*)&out[o] = make_float2(acc[jj][0] + bias0, acc[jj][1] + bias1);
    }
}

// ---------------------------------------------------------------------------
// Input order (metadata): embeds, umask, qmask, embeds_cmp, W1, b1, W2, b2
// ---------------------------------------------------------------------------
extern "C" void kernel_launch(void* const* d_in, const int* in_sizes, int n_in,
                              void* d_out, int out_size)
{
    const float* embeds     = (const float*)d_in[0];
    const float* embeds_cmp = (const float*)d_in[3];
    const float* W1         = (const float*)d_in[4];
    const float* b1         = (const float*)d_in[5];
    const float* W2         = (const float*)d_in[6];
    const float* b2         = (const float*)d_in[7];
    float* out = (float*)d_out;

    cudaFuncSetAttribute(pairwise_kernel,
                         cudaFuncAttributeMaxDynamicSharedMemorySize, kSmemB);

    gemm1_kernel<<<dim3(48, 2), 256>>>(embeds, embeds_cmp, W1);
    pairwise_kernel<<<dim3(12, 16), 256, kSmemB>>>(b1, W2, b2, out);
}